// round 8
// baseline (speedup 1.0000x reference)
#include <cuda_runtime.h>
#include <cstdint>

#define BATCH 64
#define DDIM 384
#define NPIX (BATCH*32*32)

// ---------------- scratch ----------------
__device__ float g_y4[NPIX*4];
__device__ float g_ah[BATCH*32*1024];
__device__ float g_aw[BATCH*32*1024];
__device__ float g_T [NPIX*DDIM];
__device__ float g_mx[NPIX*DDIM];
__device__ float g_wcat[768*384];
__device__ float g_bco[384];

__device__ __forceinline__ unsigned f2tf32(float f) {
    unsigned u; asm("cvt.rna.tf32.f32 %0, %1;" : "=r"(u) : "f"(f)); return u;
}
__device__ __forceinline__ unsigned long long pack2(float a) {
    unsigned long long r; asm("mov.b64 %0, {%1, %1};" : "=l"(r) : "f"(a)); return r;
}
#define FMA2(d,a,b) asm("fma.rn.f32x2 %0, %1, %2, %0;" : "+l"(d) : "l"(a), "l"(b))

// ---------------- prep ----------------
__global__ __launch_bounds__(1024) void prep_wco(const float* __restrict__ Wc,
                                                 const float* __restrict__ Wo) {
    __shared__ float sWo[32][33], sWc[32][33];
    int tx = threadIdx.x, ty = threadIdx.y;
    int o0 = blockIdx.x * 32, k0 = blockIdx.y * 32;
    float acc = 0.f;
    for (int dt = 0; dt < 12; ++dt) {
        sWo[ty][tx] = Wo[(o0 + ty)*384 + dt*32 + tx];
        sWc[ty][tx] = Wc[(dt*32 + ty)*384 + k0 + tx];
        __syncthreads();
#pragma unroll
        for (int dd = 0; dd < 32; ++dd) acc += sWo[ty][dd] * sWc[dd][tx];
        __syncthreads();
    }
    g_wcat[(k0 + tx)*384 + o0 + ty] = __uint_as_float(f2tf32(acc));
}

__global__ __launch_bounds__(1024) void prep_wot(const float* __restrict__ Wo) {
    __shared__ float s[32][33];
    int tx = threadIdx.x, ty = threadIdx.y;
    int o0 = blockIdx.x * 32, k0 = blockIdx.y * 32;
    s[ty][tx] = Wo[(o0 + ty)*384 + k0 + tx];
    __syncthreads();
    g_wcat[(384 + k0 + ty)*384 + o0 + tx] = __uint_as_float(f2tf32(s[tx][ty]));
}

__global__ void prep_bco(const float* __restrict__ Wo, const float* __restrict__ bc,
                         const float* __restrict__ bo) {
    int o = threadIdx.x;
    if (o < 384) {
        float acc = bo[o];
        for (int k = 0; k < 384; ++k) acc += Wo[o*384 + k] * bc[k];
        g_bco[o] = acc;
    }
}

// ---------------- fused 1x1 convs (E=2, h & w branches) ----------------
__global__ __launch_bounds__(256) void y4_kernel(const float* __restrict__ x,
        const float* __restrict__ W1h, const float* __restrict__ b1h,
        const float* __restrict__ W1w, const float* __restrict__ b1w) {
    int lane = threadIdx.x & 31, warp = threadIdx.x >> 5;
    int dbase = lane * 12;
    float wh0[12], wh1[12], ww0[12], ww1[12];
#pragma unroll
    for (int u = 0; u < 12; ++u) {
        wh0[u] = __ldg(W1h + dbase + u);
        wh1[u] = __ldg(W1h + 384 + dbase + u);
        ww0[u] = __ldg(W1w + dbase + u);
        ww1[u] = __ldg(W1w + 384 + dbase + u);
    }
    float bh0 = __ldg(b1h), bh1 = __ldg(b1h+1), bw0 = __ldg(b1w), bw1 = __ldg(b1w+1);
    int pbase = blockIdx.x * 128 + warp * 16;
    for (int it = 0; it < 16; ++it) {
        int p = pbase + it;
        const float4* xr = (const float4*)(x + (size_t)p*384 + dbase);
        float4 v0 = xr[0], v1 = xr[1], v2 = xr[2];
        float xv[12] = {v0.x,v0.y,v0.z,v0.w, v1.x,v1.y,v1.z,v1.w, v2.x,v2.y,v2.z,v2.w};
        float s0=0.f, s1=0.f, s2=0.f, s3=0.f;
#pragma unroll
        for (int u = 0; u < 12; ++u) {
            s0 += xv[u]*wh0[u]; s1 += xv[u]*wh1[u];
            s2 += xv[u]*ww0[u]; s3 += xv[u]*ww1[u];
        }
#pragma unroll
        for (int off = 16; off; off >>= 1) {
            s0 += __shfl_xor_sync(~0u, s0, off);
            s1 += __shfl_xor_sync(~0u, s1, off);
            s2 += __shfl_xor_sync(~0u, s2, off);
            s3 += __shfl_xor_sync(~0u, s3, off);
        }
        if (lane == 0)
            *(float4*)(g_y4 + (size_t)p*4) = make_float4(s0+bh0, s1+bh1, s2+bw0, s3+bw1);
    }
}

// ---------------- grouped-conv logits + softmax ----------------
// mode 0: block=(b,w), attn_h[b,w,i,j]; mode 1: block=(b,h), attn_w[b,h,i,j]
__global__ __launch_bounds__(1024) void attn_kernel(const float* __restrict__ W2,
                                                    const float* __restrict__ b2, int mode) {
    __shared__ float ys[2][32];
    int blk = blockIdx.x, b = blk >> 5, s = blk & 31, t = threadIdx.x;
    if (t < 64) {
        int e = t >> 5, q = t & 31;
        int pix = mode ? ((b*32 + s)*32 + q) : ((b*32 + q)*32 + s);
        ys[e][q] = g_y4[(size_t)pix*4 + (mode ? 2 : 0) + e];
    }
    __syncthreads();
    int i = t >> 5, j = t & 31;
    int e = i >> 4;
    int cb = ((i >> 2) * 8) & 31;
    const float* wrow = W2 + (size_t)(i*32 + j)*8;
    float l = __ldg(b2 + i*32 + j);
#pragma unroll
    for (int cc = 0; cc < 8; ++cc) l += __ldg(wrow + cc) * ys[e][cb + cc];
    float m = l;
#pragma unroll
    for (int off = 16; off; off >>= 1) m = fmaxf(m, __shfl_xor_sync(~0u, m, off));
    float ex = expf(l - m), sum = ex;
#pragma unroll
    for (int off = 16; off; off >>= 1) sum += __shfl_xor_sync(~0u, sum, off);
    (mode ? g_aw : g_ah)[(size_t)blk*1024 + i*32 + j] = ex / sum;
}

// ---------------- attention apply ----------------
// mode 0: T[b,i,s,:] = sum_j Ah[b,s,i,j] x[b,j,s,:]
// mode 1: mx[b,s,i,:] = T[b,s,i,:] + sum_j Aw[b,s,i,j] x[b,s,j,:]
__global__ __launch_bounds__(256) void apply_kernel(const float* __restrict__ x, int mode) {
    extern __shared__ float sm[];
    float* xs = sm;            // [32][384]
    float* as = sm + 32*384;   // [1024]
    int blk = blockIdx.x, b = blk >> 5, s = blk & 31, t = threadIdx.x;
    size_t rowbase, rowstride;
    if (mode == 0) { rowbase = ((size_t)b*1024 + s)*384;    rowstride = 32*384; }
    else           { rowbase = ((size_t)b*1024 + s*32)*384; rowstride = 384; }
    for (int l = t; l < 3072; l += 256) {
        int r = l / 96, c4 = l % 96;
        *(float4*)&xs[r*384 + c4*4] = *(const float4*)(x + rowbase + (size_t)r*rowstride + c4*4);
    }
    const float* attn = (mode ? g_aw : g_ah) + (size_t)blk*1024;
    for (int l = t; l < 1024; l += 256) as[l] = attn[l];
    __syncthreads();
    int w = t >> 5, lane = t & 31;
    unsigned long long acc[4][6];
#pragma unroll
    for (int ii = 0; ii < 4; ++ii)
#pragma unroll
        for (int q = 0; q < 6; ++q) acc[ii][q] = 0ull;
#pragma unroll 4
    for (int j = 0; j < 32; ++j) {
        ulonglong2 xv[3];
#pragma unroll
        for (int c = 0; c < 3; ++c)
            xv[c] = *(ulonglong2*)&xs[j*384 + (lane + 32*c)*4];
#pragma unroll
        for (int ii = 0; ii < 4; ++ii) {
            unsigned long long av = pack2(as[(w + 8*ii)*32 + j]);
#pragma unroll
            for (int c = 0; c < 3; ++c) {
                FMA2(acc[ii][2*c],   av, xv[c].x);
                FMA2(acc[ii][2*c+1], av, xv[c].y);
            }
        }
    }
#pragma unroll
    for (int ii = 0; ii < 4; ++ii) {
        int i = w + 8*ii;
#pragma unroll
        for (int c = 0; c < 3; ++c) {
            int d = (lane + 32*c)*4;
            float2 u0 = *(float2*)&acc[ii][2*c];
            float2 u1 = *(float2*)&acc[ii][2*c+1];
            if (mode == 0) {
                *(float4*)(g_T + ((size_t)(b*32 + i)*32 + s)*384 + d) =
                    make_float4(u0.x, u0.y, u1.x, u1.y);
            } else {
                size_t o = ((size_t)b*1024 + s*32 + i)*384 + d;
                float4 tv = *(const float4*)(g_T + o);
                *(float4*)(g_mx + o) =
                    make_float4(u0.x+tv.x, u0.y+tv.y, u1.x+tv.z, u1.y+tv.w);
            }
        }
    }
}

// ---------------- big GEMM: out[p][o] = sum_k [x|mx][p][k] * Wcat[k][o] + bco[o]
#define SA_P 24
#define SB_P 132
#define MMA(d, a, b0, b1) \
    asm("mma.sync.aligned.m16n8k8.row.col.f32.tf32.tf32.f32 " \
        "{%0,%1,%2,%3}, {%4,%5,%6,%7}, {%8,%9}, {%0,%1,%2,%3};" \
        : "+f"(d[0]), "+f"(d[1]), "+f"(d[2]), "+f"(d[3]) \
        : "r"(a[0]), "r"(a[1]), "r"(a[2]), "r"(a[3]), "r"(b0), "r"(b1))

__global__ __launch_bounds__(256) void gemm_kernel(const float* __restrict__ x,
                                                   float* __restrict__ out) {
    __shared__ __align__(16) float sA[2][128*SA_P];
    __shared__ __align__(16) float sB[2][16*SB_P];
    int t = threadIdx.x;
    int row0 = blockIdx.y * 128, col0 = blockIdx.x * 128;
    unsigned saB = (unsigned)__cvta_generic_to_shared(sA);
    unsigned sbB = (unsigned)__cvta_generic_to_shared(sB);
    auto load_stage = [&](int kt, int buf) {
        const float* Ah = (kt < 24) ? x : g_mx;
        int koff = (kt < 24) ? kt*16 : kt*16 - 384;
#pragma unroll
        for (int q = 0; q < 2; ++q) {
            int c = t + 256*q, r = c >> 2, seg = c & 3;
            const float* src = Ah + (size_t)(row0 + r)*384 + koff + seg*4;
            unsigned dst = saB + (unsigned)(buf*128*SA_P + r*SA_P + seg*4)*4u;
            asm volatile("cp.async.ca.shared.global [%0], [%1], 16;" :: "r"(dst), "l"(src));
        }
#pragma unroll
        for (int q = 0; q < 2; ++q) {
            int c = t + 256*q, r = c >> 5, seg = c & 31;
            const float* src = g_wcat + (size_t)(kt*16 + r)*384 + col0 + seg*4;
            unsigned dst = sbB + (unsigned)(buf*16*SB_P + r*SB_P + seg*4)*4u;
            asm volatile("cp.async.ca.shared.global [%0], [%1], 16;" :: "r"(dst), "l"(src));
        }
        asm volatile("cp.async.commit_group;" ::: "memory");
    };
    int lane = t & 31, w = t >> 5;
    int gid = lane >> 2, tig = lane & 3;
    int m0 = (w & 3) * 32, n0 = (w >> 2) * 64;
    float acc[2][8][4];
#pragma unroll
    for (int mt = 0; mt < 2; ++mt)
#pragma unroll
        for (int nt = 0; nt < 8; ++nt)
#pragma unroll
            for (int q = 0; q < 4; ++q) acc[mt][nt][q] = 0.f;
    load_stage(0, 0);
    for (int kt = 0; kt < 48; ++kt) {
        int buf = kt & 1;
        if (kt + 1 < 48) {
            load_stage(kt + 1, buf ^ 1);
            asm volatile("cp.async.wait_group 1;" ::: "memory");
        } else {
            asm volatile("cp.async.wait_group 0;" ::: "memory");
        }
        __syncthreads();
        const float* A = sA[buf];
        const float* Bs = sB[buf];
#pragma unroll
        for (int ks = 0; ks < 16; ks += 8) {
            unsigned af[2][4];
#pragma unroll
            for (int mt = 0; mt < 2; ++mt) {
                int rm = m0 + mt*16 + gid;
                af[mt][0] = f2tf32(A[rm*SA_P + ks + tig]);
                af[mt][1] = f2tf32(A[(rm+8)*SA_P + ks + tig]);
                af[mt][2] = f2tf32(A[rm*SA_P + ks + tig + 4]);
                af[mt][3] = f2tf32(A[(rm+8)*SA_P + ks + tig + 4]);
            }
#pragma unroll
            for (int nt = 0; nt < 8; ++nt) {
                unsigned b0 = __float_as_uint(Bs[(ks+tig)*SB_P + n0 + nt*8 + gid]);
                unsigned b1 = __float_as_uint(Bs[(ks+tig+4)*SB_P + n0 + nt*8 + gid]);
                MMA(acc[0][nt], af[0], b0, b1);
                MMA(acc[1][nt], af[1], b0, b1);
            }
        }
        __syncthreads();
    }
#pragma unroll
    for (int mt = 0; mt < 2; ++mt)
#pragma unroll
        for (int nt = 0; nt < 8; ++nt) {
            int rm = row0 + m0 + mt*16 + gid;
            int cn = col0 + n0 + nt*8 + tig*2;
            float b0 = g_bco[cn], b1v = g_bco[cn+1];
            *(float2*)(out + (size_t)rm*384 + cn) =
                make_float2(acc[mt][nt][0] + b0, acc[mt][nt][1] + b1v);
            *(float2*)(out + (size_t)(rm+8)*384 + cn) =
                make_float2(acc[mt][nt][2] + b0, acc[mt][nt][3] + b1v);
        }
}

extern "C" void kernel_launch(void* const* d_in, const int* in_sizes, int n_in,
                              void* d_out, int out_size) {
    const float* x   = (const float*)d_in[0];
    const float* Wc  = (const float*)d_in[1];
    const float* bc  = (const float*)d_in[2];
    const float* Wo  = (const float*)d_in[3];
    const float* bo  = (const float*)d_in[4];
    const float* W1h = (const float*)d_in[5];
    const float* b1h = (const float*)d_in[6];
    const float* W2h = (const float*)d_in[7];
    const float* b2h = (const float*)d_in[8];
    const float* W1w = (const float*)d_in[9];
    const float* b1w = (const float*)d_in[10];
    const float* W2w = (const float*)d_in[11];
    const float* b2w = (const float*)d_in[12];
    float* out = (float*)d_out;

    cudaFuncSetAttribute(apply_kernel, cudaFuncAttributeMaxDynamicSharedMemorySize, 53248);

    prep_wco<<<dim3(12,12), dim3(32,32)>>>(Wc, Wo);
    prep_wot<<<dim3(12,12), dim3(32,32)>>>(Wo);
    prep_bco<<<1, 384>>>(Wo, bc, bo);
    y4_kernel<<<512, 256>>>(x, W1h, b1h, W1w, b1w);
    attn_kernel<<<2048, 1024>>>(W2h, b2h, 0);
    attn_kernel<<<2048, 1024>>>(W2w, b2w, 1);
    apply_kernel<<<2048, 256, 53248>>>(x, 0);
    apply_kernel<<<2048, 256, 53248>>>(x, 1);
    gemm_kernel<<<dim3(3,512), 256>>>(x, out);
}